// round 1
// baseline (speedup 1.0000x reference)
#include <cuda_runtime.h>

#define C_DIM 512
#define T_SEQ 2048
#define B_SZ 4
#define H_NUM 8
#define DK 64
#define M_ROWS (B_SZ * T_SEQ)   // 8192

// Scratch (no allocations allowed in kernel_launch)
__device__ float g_Q[M_ROWS * C_DIM];
__device__ float g_K[M_ROWS * C_DIM];
__device__ float g_V[M_ROWS * C_DIM];
__device__ float g_CTX[M_ROWS * C_DIM];
__device__ float g_Y[M_ROWS * C_DIM];

// ---------------------------------------------------------------------------
// NT GEMM: out[m][n] = sum_k A[m][k] * B[n][k] + bias[n] (+ res[m][n])
// A: [M,K] row-major, B: [N,K] row-major. BM=BN=64, BK=16, 256 thr, 4x4 micro.
// ---------------------------------------------------------------------------
__global__ __launch_bounds__(256) void gemm_nt(
    const float* __restrict__ A, const float* __restrict__ B,
    const float* __restrict__ bias, const float* __restrict__ res,
    float* __restrict__ out, int M, int N, int K)
{
    __shared__ float As[16][68];   // [k][m], +4 pad keeps 16B alignment
    __shared__ float Bs[16][68];   // [k][n]
    const int bm = blockIdx.y * 64;
    const int bn = blockIdx.x * 64;
    const int tid = threadIdx.x;
    const int ty = tid >> 4;          // 0..15
    const int tx = tid & 15;          // 0..15
    const int lr = tid >> 2;          // 0..63 (row within tile for loads)
    const int lc = (tid & 3) << 2;    // 0,4,8,12 (k offset for loads)

    float acc[4][4] = {};
    const float* Ap = A + (size_t)(bm + lr) * K + lc;
    const float* Bp = B + (size_t)(bn + lr) * K + lc;

    for (int k0 = 0; k0 < K; k0 += 16) {
        float4 av = *(const float4*)(Ap + k0);
        float4 bv = *(const float4*)(Bp + k0);
        As[lc + 0][lr] = av.x; As[lc + 1][lr] = av.y;
        As[lc + 2][lr] = av.z; As[lc + 3][lr] = av.w;
        Bs[lc + 0][lr] = bv.x; Bs[lc + 1][lr] = bv.y;
        Bs[lc + 2][lr] = bv.z; Bs[lc + 3][lr] = bv.w;
        __syncthreads();
#pragma unroll
        for (int k = 0; k < 16; k++) {
            float4 a = *(const float4*)&As[k][ty << 2];
            float4 b = *(const float4*)&Bs[k][tx << 2];
            acc[0][0] += a.x * b.x; acc[0][1] += a.x * b.y;
            acc[0][2] += a.x * b.z; acc[0][3] += a.x * b.w;
            acc[1][0] += a.y * b.x; acc[1][1] += a.y * b.y;
            acc[1][2] += a.y * b.z; acc[1][3] += a.y * b.w;
            acc[2][0] += a.z * b.x; acc[2][1] += a.z * b.y;
            acc[2][2] += a.z * b.z; acc[2][3] += a.z * b.w;
            acc[3][0] += a.w * b.x; acc[3][1] += a.w * b.y;
            acc[3][2] += a.w * b.z; acc[3][3] += a.w * b.w;
        }
        __syncthreads();
    }

    const int ncol = bn + (tx << 2);
    float4 bb = *(const float4*)&bias[ncol];
#pragma unroll
    for (int i = 0; i < 4; i++) {
        int m = bm + (ty << 2) + i;
        float4 o;
        o.x = acc[i][0] + bb.x; o.y = acc[i][1] + bb.y;
        o.z = acc[i][2] + bb.z; o.w = acc[i][3] + bb.w;
        if (res) {
            float4 r = *(const float4*)&res[(size_t)m * N + ncol];
            o.x += r.x; o.y += r.y; o.z += r.z; o.w += r.w;
        }
        *(float4*)&out[(size_t)m * N + ncol] = o;
    }
}

// ---------------------------------------------------------------------------
// Flash-style attention: block = one (b,h) x 32-query tile, streaming softmax
// over 32-key tiles. 256 threads: 8 lanes per query row, each lane owns 8 of
// the 64 output dims. bias[q][k] = phase_bias[q%3][k%3], added after *0.125.
// ---------------------------------------------------------------------------
__global__ __launch_bounds__(256) void attn_kernel(
    const float* __restrict__ Q, const float* __restrict__ Kg,
    const float* __restrict__ Vg, const float* __restrict__ pb,
    float* __restrict__ ctx)
{
    __shared__ float Qs[32][68];
    __shared__ float Ks[32][68];
    __shared__ float Vs[32][68];
    __shared__ float Ps[32][33];
    __shared__ float bs[9];

    const int h = blockIdx.y, b = blockIdx.z;
    const int q0 = blockIdx.x * 32;
    const int tid = threadIdx.x;
    const int row = tid >> 3;   // 0..31 query within tile
    const int sub = tid & 7;    // 0..7 lane within row group

    if (tid < 9) bs[tid] = pb[tid];

    // load Q tile [32 x 64]
    {
        int f = tid;
#pragma unroll
        for (int it = 0; it < 2; it++, f += 256) {
            int r = f >> 4, d = (f & 15) << 2;
            *(float4*)&Qs[r][d] =
                *(const float4*)&Q[(size_t)(b * T_SEQ + q0 + r) * C_DIM + h * DK + d];
        }
    }
    const int qmod = (q0 + row) % 3;
    float m = -1e30f, l = 0.f;
    float o[8] = {};
    __syncthreads();

    for (int kt = 0; kt < T_SEQ; kt += 32) {
        // load K,V tiles
        int f = tid;
#pragma unroll
        for (int it = 0; it < 2; it++, f += 256) {
            int r = f >> 4, d = (f & 15) << 2;
            size_t gi = (size_t)(b * T_SEQ + kt + r) * C_DIM + h * DK + d;
            *(float4*)&Ks[r][d] = *(const float4*)&Kg[gi];
            *(float4*)&Vs[r][d] = *(const float4*)&Vg[gi];
        }
        __syncthreads();

        // S = Q K^T for this lane's 4 keys: k = sub + 8j
        float s[4] = {};
#pragma unroll
        for (int d4 = 0; d4 < 16; d4++) {
            float4 qv = *(const float4*)&Qs[row][d4 << 2];
#pragma unroll
            for (int j = 0; j < 4; j++) {
                float4 kv = *(const float4*)&Ks[sub + (j << 3)][d4 << 2];
                s[j] += qv.x * kv.x + qv.y * kv.y + qv.z * kv.z + qv.w * kv.w;
            }
        }
        // scale + phase bias + tile max
        float mt = -1e30f;
#pragma unroll
        for (int j = 0; j < 4; j++) {
            int kg = kt + sub + (j << 3);
            s[j] = s[j] * 0.125f + bs[qmod * 3 + (kg % 3)];
            mt = fmaxf(mt, s[j]);
        }
        mt = fmaxf(mt, __shfl_xor_sync(0xffffffffu, mt, 1, 8));
        mt = fmaxf(mt, __shfl_xor_sync(0xffffffffu, mt, 2, 8));
        mt = fmaxf(mt, __shfl_xor_sync(0xffffffffu, mt, 4, 8));

        float mn = fmaxf(m, mt);
        float alpha = __expf(m - mn);
        m = mn;
        float ls = 0.f;
#pragma unroll
        for (int j = 0; j < 4; j++) {
            float p = __expf(s[j] - mn);
            Ps[row][sub + (j << 3)] = p;
            ls += p;
        }
        ls += __shfl_xor_sync(0xffffffffu, ls, 1, 8);
        ls += __shfl_xor_sync(0xffffffffu, ls, 2, 8);
        ls += __shfl_xor_sync(0xffffffffu, ls, 4, 8);
        l = l * alpha + ls;
#pragma unroll
        for (int i = 0; i < 8; i++) o[i] *= alpha;
        __syncwarp();

        // O += P V  (this lane's 8 dims: sub*8 .. sub*8+7)
#pragma unroll
        for (int k = 0; k < 32; k++) {
            float p = Ps[row][k];
            float4 v0 = *(const float4*)&Vs[k][sub << 3];
            float4 v1 = *(const float4*)&Vs[k][(sub << 3) + 4];
            o[0] += p * v0.x; o[1] += p * v0.y; o[2] += p * v0.z; o[3] += p * v0.w;
            o[4] += p * v1.x; o[5] += p * v1.y; o[6] += p * v1.z; o[7] += p * v1.w;
        }
        __syncthreads();
    }

    float inv = 1.f / l;
    size_t oi = (size_t)(b * T_SEQ + q0 + row) * C_DIM + h * DK + (sub << 3);
    float4 w0 = make_float4(o[0] * inv, o[1] * inv, o[2] * inv, o[3] * inv);
    float4 w1 = make_float4(o[4] * inv, o[5] * inv, o[6] * inv, o[7] * inv);
    *(float4*)&ctx[oi] = w0;
    *(float4*)&ctx[oi + 4] = w1;
}

// ---------------------------------------------------------------------------
// LayerNorm: one block (128 thr) per row of 512.
// ---------------------------------------------------------------------------
__global__ __launch_bounds__(128) void ln_kernel(
    const float* __restrict__ in, const float* __restrict__ g,
    const float* __restrict__ bta, float* __restrict__ out)
{
    __shared__ float r1[4], r2[4];
    const size_t rowb = (size_t)blockIdx.x * C_DIM;
    const int tid = threadIdx.x;

    float4 v = *(const float4*)&in[rowb + (tid << 2)];
    float s = v.x + v.y + v.z + v.w;
#pragma unroll
    for (int off = 16; off; off >>= 1) s += __shfl_xor_sync(~0u, s, off);
    if ((tid & 31) == 0) r1[tid >> 5] = s;
    __syncthreads();
    float mu = (r1[0] + r1[1] + r1[2] + r1[3]) * (1.f / C_DIM);

    float dx = v.x - mu, dy = v.y - mu, dz = v.z - mu, dw = v.w - mu;
    float ss = dx * dx + dy * dy + dz * dz + dw * dw;
#pragma unroll
    for (int off = 16; off; off >>= 1) ss += __shfl_xor_sync(~0u, ss, off);
    if ((tid & 31) == 0) r2[tid >> 5] = ss;
    __syncthreads();
    float inv = rsqrtf((r2[0] + r2[1] + r2[2] + r2[3]) * (1.f / C_DIM) + 1e-5f);

    float4 gg = *(const float4*)&g[tid << 2];
    float4 bb = *(const float4*)&bta[tid << 2];
    float4 o4;
    o4.x = dx * inv * gg.x + bb.x;
    o4.y = dy * inv * gg.y + bb.y;
    o4.z = dz * inv * gg.z + bb.z;
    o4.w = dw * inv * gg.w + bb.w;
    *(float4*)&out[rowb + (tid << 2)] = o4;
}

// ---------------------------------------------------------------------------
extern "C" void kernel_launch(void* const* d_in, const int* in_sizes, int n_in,
                              void* d_out, int out_size)
{
    const float* x  = (const float*)d_in[0];
    const float* Wq = (const float*)d_in[1];
    const float* bq = (const float*)d_in[2];
    const float* Wk = (const float*)d_in[3];
    const float* bk = (const float*)d_in[4];
    const float* Wv = (const float*)d_in[5];
    const float* bv = (const float*)d_in[6];
    const float* Wo = (const float*)d_in[7];
    const float* bo = (const float*)d_in[8];
    const float* pb = (const float*)d_in[9];
    const float* lg = (const float*)d_in[10];
    const float* lb = (const float*)d_in[11];
    float* out = (float*)d_out;

    float *q, *k, *v, *ctx, *y;
    cudaGetSymbolAddress((void**)&q,   g_Q);
    cudaGetSymbolAddress((void**)&k,   g_K);
    cudaGetSymbolAddress((void**)&v,   g_V);
    cudaGetSymbolAddress((void**)&ctx, g_CTX);
    cudaGetSymbolAddress((void**)&y,   g_Y);

    dim3 gg(C_DIM / 64, M_ROWS / 64);     // (8, 128)
    gemm_nt<<<gg, 256>>>(x, Wq, bq, nullptr, q, M_ROWS, C_DIM, C_DIM);
    gemm_nt<<<gg, 256>>>(x, Wk, bk, nullptr, k, M_ROWS, C_DIM, C_DIM);
    gemm_nt<<<gg, 256>>>(x, Wv, bv, nullptr, v, M_ROWS, C_DIM, C_DIM);

    attn_kernel<<<dim3(T_SEQ / 32, H_NUM, B_SZ), 256>>>(q, k, v, pb, ctx);

    gemm_nt<<<gg, 256>>>(ctx, Wo, bo, x, y, M_ROWS, C_DIM, C_DIM);

    ln_kernel<<<M_ROWS, 128>>>(y, lg, lb, out);
}

// round 5
// speedup vs baseline: 3.9007x; 3.9007x over previous
#include <cuda_runtime.h>
#include <cstdint>

#define C_DIM 512
#define T_SEQ 2048
#define B_SZ 4
#define H_NUM 8
#define DK 64
#define M_ROWS (B_SZ * T_SEQ)   // 8192

__device__ float g_Q[M_ROWS * C_DIM];
__device__ float g_K[M_ROWS * C_DIM];
__device__ float g_V[M_ROWS * C_DIM];
__device__ float g_CTX[M_ROWS * C_DIM];
__device__ float g_Y[M_ROWS * C_DIM];

// ---------------------------------------------------------------------------
// helpers
// ---------------------------------------------------------------------------
__device__ __forceinline__ uint32_t f2tf(float x) {
    uint32_t r; asm("cvt.rna.tf32.f32 %0, %1;" : "=r"(r) : "f"(x)); return r;
}
__device__ __forceinline__ void mma8(float* c,
    uint32_t a0, uint32_t a1, uint32_t a2, uint32_t a3,
    uint32_t b0, uint32_t b1)
{
    asm volatile(
        "mma.sync.aligned.m16n8k8.row.col.f32.tf32.tf32.f32 "
        "{%0,%1,%2,%3}, {%4,%5,%6,%7}, {%8,%9}, {%0,%1,%2,%3};"
        : "+f"(c[0]), "+f"(c[1]), "+f"(c[2]), "+f"(c[3])
        : "r"(a0), "r"(a1), "r"(a2), "r"(a3), "r"(b0), "r"(b1));
}

// FFMA-only exp; args bounded (|x| <~ 16)
__device__ __forceinline__ float fexp(float x) {
    const float L2E = 1.4426950408889634f;
    float t  = fmaf(x, L2E, 12582912.0f);
    float tn = t - 12582912.0f;
    float f  = fmaf(x, L2E, -tn);
    uint32_t sc = (__float_as_uint(t) << 23) + 0x3F800000u;
    float p = fmaf(f, 0.0013333558f, 0.0096181291f);
    p = fmaf(f, p, 0.0555041087f);
    p = fmaf(f, p, 0.2402265069f);
    p = fmaf(f, p, 0.6931471806f);
    p = fmaf(f, p, 1.0f);
    return p * __uint_as_float(sc);
}

// ---------------------------------------------------------------------------
// 3xTF32 GEMM: out[m][n] = sum_k A[m][k]*W[n][k] + bias[n] (+res[m][n])
// Tile 128x64, BK=32, 256 thr, 8 warps (wm=w&3, wn=w>>2) own 32x32 each.
// Static smem 27.6KB.
// ---------------------------------------------------------------------------
__global__ __launch_bounds__(256) void gemm_mma(
    const float* __restrict__ A, const float* __restrict__ W,
    const float* __restrict__ bias, const float* __restrict__ res,
    float* __restrict__ out)
{
    __shared__ float As[128 * 36];
    __shared__ float Ws[64 * 36];
    const int tid = threadIdx.x, w = tid >> 5, lid = tid & 31;
    const int g = lid >> 2, tig = lid & 3;
    const int wm = w & 3, wn = w >> 2;
    const int bm = blockIdx.y * 128, bn = blockIdx.x * 64;

    float acc[2][4][4] = {};

    for (int k0 = 0; k0 < C_DIM; k0 += 32) {
        __syncthreads();
#pragma unroll
        for (int it = 0; it < 4; it++) {
            int f = tid + it * 256; int r = f >> 3; int c4 = (f & 7) << 2;
            *(float4*)&As[r * 36 + c4] =
                *(const float4*)(A + (size_t)(bm + r) * C_DIM + k0 + c4);
        }
#pragma unroll
        for (int it = 0; it < 2; it++) {
            int f = tid + it * 256; int r = f >> 3; int c4 = (f & 7) << 2;
            *(float4*)&Ws[r * 36 + c4] =
                *(const float4*)(W + (size_t)(bn + r) * C_DIM + k0 + c4);
        }
        __syncthreads();

#pragma unroll
        for (int kk = 0; kk < 4; kk++) {
            uint32_t ah[2][4], al[2][4];
#pragma unroll
            for (int i = 0; i < 2; i++) {
                const float* ap = &As[(wm * 32 + i * 16 + g) * 36 + kk * 8 + tig];
                float a0 = ap[0], a1 = ap[8 * 36], a2 = ap[4], a3 = ap[8 * 36 + 4];
                ah[i][0] = f2tf(a0); al[i][0] = f2tf(a0 - __uint_as_float(ah[i][0]));
                ah[i][1] = f2tf(a1); al[i][1] = f2tf(a1 - __uint_as_float(ah[i][1]));
                ah[i][2] = f2tf(a2); al[i][2] = f2tf(a2 - __uint_as_float(ah[i][2]));
                ah[i][3] = f2tf(a3); al[i][3] = f2tf(a3 - __uint_as_float(ah[i][3]));
            }
#pragma unroll
            for (int j = 0; j < 4; j++) {
                const float* bp = &Ws[(wn * 32 + j * 8 + g) * 36 + kk * 8 + tig];
                float b0 = bp[0], b1 = bp[4];
                uint32_t bh0 = f2tf(b0), bh1 = f2tf(b1);
                uint32_t bl0 = f2tf(b0 - __uint_as_float(bh0));
                uint32_t bl1 = f2tf(b1 - __uint_as_float(bh1));
#pragma unroll
                for (int i = 0; i < 2; i++) {
                    mma8(acc[i][j], ah[i][0], ah[i][1], ah[i][2], ah[i][3], bh0, bh1);
                    mma8(acc[i][j], ah[i][0], ah[i][1], ah[i][2], ah[i][3], bl0, bl1);
                    mma8(acc[i][j], al[i][0], al[i][1], al[i][2], al[i][3], bh0, bh1);
                }
            }
        }
    }

#pragma unroll
    for (int i = 0; i < 2; i++) {
#pragma unroll
        for (int j = 0; j < 4; j++) {
            int r0 = bm + wm * 32 + i * 16 + g;
            int c  = bn + wn * 32 + j * 8 + 2 * tig;
            float2 bb = *(const float2*)&bias[c];
            float2 o0 = make_float2(acc[i][j][0] + bb.x, acc[i][j][1] + bb.y);
            float2 o1 = make_float2(acc[i][j][2] + bb.x, acc[i][j][3] + bb.y);
            if (res) {
                float2 ra = *(const float2*)&res[(size_t)r0 * C_DIM + c];
                float2 rb = *(const float2*)&res[(size_t)(r0 + 8) * C_DIM + c];
                o0.x += ra.x; o0.y += ra.y; o1.x += rb.x; o1.y += rb.y;
            }
            *(float2*)&out[(size_t)r0 * C_DIM + c] = o0;
            *(float2*)&out[(size_t)(r0 + 8) * C_DIM + c] = o1;
        }
    }
}

// ---------------------------------------------------------------------------
// Attention via mma.sync tf32. CTA = (b, h, 64 queries); 4 warps x 16 rows.
// 64 key tiles of 32. S = 3xTF32; softmax (no max-sub, bounded logits);
// P smem roundtrip (warp-local); ctx += P*V (1-pass tf32) in registers.
// Static smem: Qs 64*68 | Ks 32*68 | Vs 32*72 | Ps 64*36 = 44580 B (< 48K,
// no opt-in, no cudaFuncSetAttribute needed).
// ---------------------------------------------------------------------------
__global__ __launch_bounds__(128) void attn_mma(
    const float* __restrict__ Qg, const float* __restrict__ Kg,
    const float* __restrict__ Vg, const float* __restrict__ pb,
    float* __restrict__ ctx)
{
    __shared__ float Qs[64 * 68];
    __shared__ float Ks[32 * 68];
    __shared__ float Vs[32 * 72];
    __shared__ float Ps[64 * 36];
    __shared__ float pbs[9];

    const int tid = threadIdx.x, w = tid >> 5, lid = tid & 31;
    const int g = lid >> 2, tig = lid & 3;
    const int h = blockIdx.y, b = blockIdx.z, q0 = blockIdx.x * 64;

    if (tid < 9) pbs[tid] = pb[tid];

    // Q tile 64x64
#pragma unroll
    for (int it = 0; it < 8; it++) {
        int f = tid + it * 128; int r = f >> 4; int c4 = (f & 15) << 2;
        *(float4*)&Qs[r * 68 + c4] =
            *(const float4*)(Qg + (size_t)(b * T_SEQ + q0 + r) * C_DIM + h * DK + c4);
    }

    const int qrow = 16 * w + g;
    const int qm0 = (q0 + qrow) % 3;
    const int qm8 = (qm0 + 2) % 3;
    const float* qbase = &Qs[qrow * 68 + tig];
    const float* pbase = &Ps[qrow * 36 + tig];

    float cacc[8][4] = {};
    float lg = 0.f, lh = 0.f;

    for (int kt = 0; kt < T_SEQ; kt += 32) {
        __syncthreads();
        // K, V tiles 32x64
#pragma unroll
        for (int it = 0; it < 4; it++) {
            int f = tid + it * 128; int r = f >> 4; int c4 = (f & 15) << 2;
            size_t gi = (size_t)(b * T_SEQ + kt + r) * C_DIM + h * DK + c4;
            *(float4*)&Ks[r * 68 + c4] = *(const float4*)(Kg + gi);
            *(float4*)&Vs[r * 72 + c4] = *(const float4*)(Vg + gi);
        }
        __syncthreads();

        // S = Q K^T (3xTF32): sacc[j] = 16x8 tile over keys kt+j*8..
        float sacc[4][4] = {};
#pragma unroll
        for (int kk = 0; kk < 8; kk++) {
            float a0 = qbase[kk * 8], a1 = qbase[kk * 8 + 8 * 68];
            float a2 = qbase[kk * 8 + 4], a3 = qbase[kk * 8 + 8 * 68 + 4];
            uint32_t ah0 = f2tf(a0), ah1 = f2tf(a1), ah2 = f2tf(a2), ah3 = f2tf(a3);
            uint32_t al0 = f2tf(a0 - __uint_as_float(ah0));
            uint32_t al1 = f2tf(a1 - __uint_as_float(ah1));
            uint32_t al2 = f2tf(a2 - __uint_as_float(ah2));
            uint32_t al3 = f2tf(a3 - __uint_as_float(ah3));
#pragma unroll
            for (int j = 0; j < 4; j++) {
                const float* bp = &Ks[(j * 8 + g) * 68 + kk * 8 + tig];
                float b0 = bp[0], b1 = bp[4];
                uint32_t bh0 = f2tf(b0), bh1 = f2tf(b1);
                uint32_t bl0 = f2tf(b0 - __uint_as_float(bh0));
                uint32_t bl1 = f2tf(b1 - __uint_as_float(bh1));
                mma8(sacc[j], ah0, ah1, ah2, ah3, bh0, bh1);
                mma8(sacc[j], ah0, ah1, ah2, ah3, bl0, bl1);
                mma8(sacc[j], al0, al1, al2, al3, bh0, bh1);
            }
        }

        // softmax + P store (warp-local rows)
        const int ktm = kt % 3;
#pragma unroll
        for (int j = 0; j < 4; j++) {
            int c3 = (ktm + j * 8 + 2 * tig) % 3;
            int c3b = (c3 + 1 == 3) ? 0 : c3 + 1;
            float p0 = fexp(fmaf(sacc[j][0], 0.125f, pbs[qm0 * 3 + c3]));
            float p1 = fexp(fmaf(sacc[j][1], 0.125f, pbs[qm0 * 3 + c3b]));
            float p2 = fexp(fmaf(sacc[j][2], 0.125f, pbs[qm8 * 3 + c3]));
            float p3 = fexp(fmaf(sacc[j][3], 0.125f, pbs[qm8 * 3 + c3b]));
            lg += p0 + p1; lh += p2 + p3;
            *(float2*)&Ps[qrow * 36 + j * 8 + 2 * tig]       = make_float2(p0, p1);
            *(float2*)&Ps[(qrow + 8) * 36 + j * 8 + 2 * tig] = make_float2(p2, p3);
        }
        __syncwarp();

        // ctx += P V (1-pass tf32): k = 32 keys (4 chunks), n = 64 dims (8 tiles)
#pragma unroll
        for (int kk = 0; kk < 4; kk++) {
            uint32_t ah0 = f2tf(pbase[kk * 8]);
            uint32_t ah1 = f2tf(pbase[kk * 8 + 8 * 36]);
            uint32_t ah2 = f2tf(pbase[kk * 8 + 4]);
            uint32_t ah3 = f2tf(pbase[kk * 8 + 8 * 36 + 4]);
#pragma unroll
            for (int j = 0; j < 8; j++) {
                const float* vp = &Vs[(kk * 8 + tig) * 72 + j * 8 + g];
                mma8(cacc[j], ah0, ah1, ah2, ah3, f2tf(vp[0]), f2tf(vp[4 * 72]));
            }
        }
    }

    // row-sum reduce over the 4 lanes of each row group
    lg += __shfl_xor_sync(~0u, lg, 1); lg += __shfl_xor_sync(~0u, lg, 2);
    lh += __shfl_xor_sync(~0u, lh, 1); lh += __shfl_xor_sync(~0u, lh, 2);
    float ig = 1.f / lg, ih = 1.f / lh;

    size_t rb = (size_t)(b * T_SEQ + q0 + qrow) * C_DIM + h * DK;
#pragma unroll
    for (int j = 0; j < 8; j++) {
        int c = j * 8 + 2 * tig;
        *(float2*)&ctx[rb + c] = make_float2(cacc[j][0] * ig, cacc[j][1] * ig);
        *(float2*)&ctx[rb + 8 * C_DIM + c] = make_float2(cacc[j][2] * ih, cacc[j][3] * ih);
    }
}

// ---------------------------------------------------------------------------
// LayerNorm: one block (128 thr) per row of 512.
// ---------------------------------------------------------------------------
__global__ __launch_bounds__(128) void ln_kernel(
    const float* __restrict__ in, const float* __restrict__ g,
    const float* __restrict__ bta, float* __restrict__ out)
{
    __shared__ float r1[4], r2[4];
    const size_t rowb = (size_t)blockIdx.x * C_DIM;
    const int tid = threadIdx.x;

    float4 v = *(const float4*)&in[rowb + (tid << 2)];
    float s = v.x + v.y + v.z + v.w;
#pragma unroll
    for (int off = 16; off; off >>= 1) s += __shfl_xor_sync(~0u, s, off);
    if ((tid & 31) == 0) r1[tid >> 5] = s;
    __syncthreads();
    float mu = (r1[0] + r1[1] + r1[2] + r1[3]) * (1.f / C_DIM);

    float dx = v.x - mu, dy = v.y - mu, dz = v.z - mu, dw = v.w - mu;
    float ss = dx * dx + dy * dy + dz * dz + dw * dw;
#pragma unroll
    for (int off = 16; off; off >>= 1) ss += __shfl_xor_sync(~0u, ss, off);
    if ((tid & 31) == 0) r2[tid >> 5] = ss;
    __syncthreads();
    float inv = rsqrtf((r2[0] + r2[1] + r2[2] + r2[3]) * (1.f / C_DIM) + 1e-5f);

    float4 gg = *(const float4*)&g[tid << 2];
    float4 bb = *(const float4*)&bta[tid << 2];
    float4 o4;
    o4.x = dx * inv * gg.x + bb.x;
    o4.y = dy * inv * gg.y + bb.y;
    o4.z = dz * inv * gg.z + bb.z;
    o4.w = dw * inv * gg.w + bb.w;
    *(float4*)&out[rowb + (tid << 2)] = o4;
}

// ---------------------------------------------------------------------------
extern "C" void kernel_launch(void* const* d_in, const int* in_sizes, int n_in,
                              void* d_out, int out_size)
{
    const float* x  = (const float*)d_in[0];
    const float* Wq = (const float*)d_in[1];
    const float* bq = (const float*)d_in[2];
    const float* Wk = (const float*)d_in[3];
    const float* bk = (const float*)d_in[4];
    const float* Wv = (const float*)d_in[5];
    const float* bv = (const float*)d_in[6];
    const float* Wo = (const float*)d_in[7];
    const float* bo = (const float*)d_in[8];
    const float* pb = (const float*)d_in[9];
    const float* lg = (const float*)d_in[10];
    const float* lb = (const float*)d_in[11];
    float* out = (float*)d_out;

    float *q, *k, *v, *ctx, *y;
    cudaGetSymbolAddress((void**)&q,   g_Q);
    cudaGetSymbolAddress((void**)&k,   g_K);
    cudaGetSymbolAddress((void**)&v,   g_V);
    cudaGetSymbolAddress((void**)&ctx, g_CTX);
    cudaGetSymbolAddress((void**)&y,   g_Y);

    dim3 gg(C_DIM / 64, M_ROWS / 128);   // (8, 64)
    gemm_mma<<<gg, 256>>>(x, Wq, bq, nullptr, q);
    gemm_mma<<<gg, 256>>>(x, Wk, bk, nullptr, k);
    gemm_mma<<<gg, 256>>>(x, Wv, bv, nullptr, v);

    attn_mma<<<dim3(T_SEQ / 64, H_NUM, B_SZ), 128>>>(q, k, v, pb, ctx);

    gemm_mma<<<gg, 256>>>(ctx, Wo, bo, x, y);

    ln_kernel<<<M_ROWS, 128>>>(y, lg, lb, out);
}

// round 8
// speedup vs baseline: 4.5945x; 1.1779x over previous
#include <cuda_runtime.h>
#include <cstdint>

#define C_DIM 512
#define T_SEQ 2048
#define B_SZ 4
#define H_NUM 8
#define DK 64
#define M_ROWS (B_SZ * T_SEQ)   // 8192

__device__ float g_Q[M_ROWS * C_DIM];
__device__ float g_K[M_ROWS * C_DIM];
__device__ float g_V[M_ROWS * C_DIM];
__device__ float g_CTX[M_ROWS * C_DIM];
__device__ float g_Y[M_ROWS * C_DIM];

// ---------------------------------------------------------------------------
// helpers
// ---------------------------------------------------------------------------
__device__ __forceinline__ uint32_t f2tf(float x) {
    uint32_t r; asm("cvt.rna.tf32.f32 %0, %1;" : "=r"(r) : "f"(x)); return r;
}
__device__ __forceinline__ float tfr(float x) {           // tf32-rounded float
    return __uint_as_float(f2tf(x));
}
__device__ __forceinline__ void mma8(float* c,
    uint32_t a0, uint32_t a1, uint32_t a2, uint32_t a3,
    uint32_t b0, uint32_t b1)
{
    asm volatile(
        "mma.sync.aligned.m16n8k8.row.col.f32.tf32.tf32.f32 "
        "{%0,%1,%2,%3}, {%4,%5,%6,%7}, {%8,%9}, {%0,%1,%2,%3};"
        : "+f"(c[0]), "+f"(c[1]), "+f"(c[2]), "+f"(c[3])
        : "r"(a0), "r"(a1), "r"(a2), "r"(a3), "r"(b0), "r"(b1));
}
__device__ __forceinline__ uint32_t fbits(float x) { return __float_as_uint(x); }

// FFMA-only exp; args bounded (|x| <~ 16)
__device__ __forceinline__ float fexp(float x) {
    const float L2E = 1.4426950408889634f;
    float t  = fmaf(x, L2E, 12582912.0f);
    float tn = t - 12582912.0f;
    float f  = fmaf(x, L2E, -tn);
    uint32_t sc = (__float_as_uint(t) << 23) + 0x3F800000u;
    float p = fmaf(f, 0.0013333558f, 0.0096181291f);
    p = fmaf(f, p, 0.0555041087f);
    p = fmaf(f, p, 0.2402265069f);
    p = fmaf(f, p, 0.6931471806f);
    p = fmaf(f, p, 1.0f);
    return p * __uint_as_float(sc);
}

// ---------------------------------------------------------------------------
// 3xTF32 GEMM, BK=16, hi/lo tiles precomputed in smem (no cvt in mainloop).
// out[m][n] = sum_k A[m][k]*W[n][k] + bias[n] (+res[m][n])
// Tile 128x64, 256 thr, 8 warps (wm=w&3, wn=w>>2) own 32x32 each.
// Static smem: (128+64)*20*2 floats = 30720 B.
// ---------------------------------------------------------------------------
__global__ __launch_bounds__(256) void gemm_mma(
    const float* __restrict__ A, const float* __restrict__ W,
    const float* __restrict__ bias, const float* __restrict__ res,
    float* __restrict__ out)
{
    __shared__ float Ah[128 * 20], Al[128 * 20];
    __shared__ float Wh[64 * 20],  Wl[64 * 20];
    const int tid = threadIdx.x, w = tid >> 5, lid = tid & 31;
    const int g = lid >> 2, tig = lid & 3;
    const int wm = w & 3, wn = w >> 2;
    const int bm = blockIdx.y * 128, bn = blockIdx.x * 64;

    float acc[2][4][4] = {};

    for (int k0 = 0; k0 < C_DIM; k0 += 16) {
        __syncthreads();
        // A chunk 128x16: 2 float4 per thread, split hi/lo at load
#pragma unroll
        for (int it = 0; it < 2; it++) {
            int f = tid + it * 256; int r = f >> 2; int c4 = (f & 3) << 2;
            float4 v = *(const float4*)(A + (size_t)(bm + r) * C_DIM + k0 + c4);
            float4 hi = make_float4(tfr(v.x), tfr(v.y), tfr(v.z), tfr(v.w));
            float4 lo = make_float4(tfr(v.x - hi.x), tfr(v.y - hi.y),
                                    tfr(v.z - hi.z), tfr(v.w - hi.w));
            *(float4*)&Ah[r * 20 + c4] = hi;
            *(float4*)&Al[r * 20 + c4] = lo;
        }
        // W chunk 64x16: 1 float4 per thread
        {
            int r = tid >> 2; int c4 = (tid & 3) << 2;
            float4 v = *(const float4*)(W + (size_t)(bn + r) * C_DIM + k0 + c4);
            float4 hi = make_float4(tfr(v.x), tfr(v.y), tfr(v.z), tfr(v.w));
            float4 lo = make_float4(tfr(v.x - hi.x), tfr(v.y - hi.y),
                                    tfr(v.z - hi.z), tfr(v.w - hi.w));
            *(float4*)&Wh[r * 20 + c4] = hi;
            *(float4*)&Wl[r * 20 + c4] = lo;
        }
        __syncthreads();

#pragma unroll
        for (int kk = 0; kk < 2; kk++) {
            uint32_t ah[2][4], al[2][4];
#pragma unroll
            for (int i = 0; i < 2; i++) {
                int ro = (wm * 32 + i * 16 + g) * 20 + kk * 8 + tig;
                ah[i][0] = fbits(Ah[ro]);          al[i][0] = fbits(Al[ro]);
                ah[i][1] = fbits(Ah[ro + 8 * 20]); al[i][1] = fbits(Al[ro + 8 * 20]);
                ah[i][2] = fbits(Ah[ro + 4]);      al[i][2] = fbits(Al[ro + 4]);
                ah[i][3] = fbits(Ah[ro + 8 * 20 + 4]); al[i][3] = fbits(Al[ro + 8 * 20 + 4]);
            }
#pragma unroll
            for (int j = 0; j < 4; j++) {
                int co = (wn * 32 + j * 8 + g) * 20 + kk * 8 + tig;
                uint32_t bh0 = fbits(Wh[co]), bh1 = fbits(Wh[co + 4]);
                uint32_t bl0 = fbits(Wl[co]), bl1 = fbits(Wl[co + 4]);
#pragma unroll
                for (int i = 0; i < 2; i++) {
                    mma8(acc[i][j], ah[i][0], ah[i][1], ah[i][2], ah[i][3], bh0, bh1);
                    mma8(acc[i][j], ah[i][0], ah[i][1], ah[i][2], ah[i][3], bl0, bl1);
                    mma8(acc[i][j], al[i][0], al[i][1], al[i][2], al[i][3], bh0, bh1);
                }
            }
        }
    }

#pragma unroll
    for (int i = 0; i < 2; i++) {
#pragma unroll
        for (int j = 0; j < 4; j++) {
            int r0 = bm + wm * 32 + i * 16 + g;
            int c  = bn + wn * 32 + j * 8 + 2 * tig;
            float2 bb = *(const float2*)&bias[c];
            float2 o0 = make_float2(acc[i][j][0] + bb.x, acc[i][j][1] + bb.y);
            float2 o1 = make_float2(acc[i][j][2] + bb.x, acc[i][j][3] + bb.y);
            if (res) {
                float2 ra = *(const float2*)&res[(size_t)r0 * C_DIM + c];
                float2 rb = *(const float2*)&res[(size_t)(r0 + 8) * C_DIM + c];
                o0.x += ra.x; o0.y += ra.y; o1.x += rb.x; o1.y += rb.y;
            }
            *(float2*)&out[(size_t)r0 * C_DIM + c] = o0;
            *(float2*)&out[(size_t)(r0 + 8) * C_DIM + c] = o1;
        }
    }
}

// ---------------------------------------------------------------------------
// Attention, 1-pass tf32 mma, all conversions hoisted to tile-load time.
// CTA = (b, h, 64 queries); 4 warps x 16 rows; 64 key tiles of 32.
// Static smem: Qt 64*68 | Kt 32*68 | Vt 32*72 | Pt 64*36 = 44548 B.
// ---------------------------------------------------------------------------
__global__ __launch_bounds__(128) void attn_mma(
    const float* __restrict__ Qg, const float* __restrict__ Kg,
    const float* __restrict__ Vg, const float* __restrict__ pb,
    float* __restrict__ ctx)
{
    __shared__ float Qt[64 * 68];
    __shared__ float Kt[32 * 68];
    __shared__ float Vt[32 * 72];
    __shared__ float Pt[64 * 36];
    __shared__ float pbs[9];

    const int tid = threadIdx.x, w = tid >> 5, lid = tid & 31;
    const int g = lid >> 2, tig = lid & 3;
    const int h = blockIdx.y, b = blockIdx.z, q0 = blockIdx.x * 64;

    if (tid < 9) pbs[tid] = pb[tid];

    // Q tile 64x64, tf32-rounded at store
#pragma unroll
    for (int it = 0; it < 8; it++) {
        int f = tid + it * 128; int r = f >> 4; int c4 = (f & 15) << 2;
        float4 v = *(const float4*)(Qg + (size_t)(b * T_SEQ + q0 + r) * C_DIM + h * DK + c4);
        *(float4*)&Qt[r * 68 + c4] =
            make_float4(tfr(v.x), tfr(v.y), tfr(v.z), tfr(v.w));
    }

    const int qrow = 16 * w + g;
    const int qm0 = (q0 + qrow) % 3;
    const int qm8 = (qm0 + 2) % 3;
    const float* qbase = &Qt[qrow * 68 + tig];
    const float* pbase = &Pt[qrow * 36 + tig];

    float cacc[8][4] = {};
    float lg = 0.f, lh = 0.f;

    for (int kt = 0; kt < T_SEQ; kt += 32) {
        __syncthreads();
        // K, V tiles 32x64, tf32-rounded at store
#pragma unroll
        for (int it = 0; it < 4; it++) {
            int f = tid + it * 128; int r = f >> 4; int c4 = (f & 15) << 2;
            size_t gi = (size_t)(b * T_SEQ + kt + r) * C_DIM + h * DK + c4;
            float4 kv = *(const float4*)(Kg + gi);
            float4 vv = *(const float4*)(Vg + gi);
            *(float4*)&Kt[r * 68 + c4] =
                make_float4(tfr(kv.x), tfr(kv.y), tfr(kv.z), tfr(kv.w));
            *(float4*)&Vt[r * 72 + c4] =
                make_float4(tfr(vv.x), tfr(vv.y), tfr(vv.z), tfr(vv.w));
        }
        __syncthreads();

        // S = Q K^T (1-pass tf32): pure LDS + MMA
        float sacc[4][4] = {};
#pragma unroll
        for (int kk = 0; kk < 8; kk++) {
            uint32_t a0 = fbits(qbase[kk * 8]);
            uint32_t a1 = fbits(qbase[kk * 8 + 8 * 68]);
            uint32_t a2 = fbits(qbase[kk * 8 + 4]);
            uint32_t a3 = fbits(qbase[kk * 8 + 8 * 68 + 4]);
#pragma unroll
            for (int j = 0; j < 4; j++) {
                const float* bp = &Kt[(j * 8 + g) * 68 + kk * 8 + tig];
                mma8(sacc[j], a0, a1, a2, a3, fbits(bp[0]), fbits(bp[4]));
            }
        }

        // softmax + P store (warp-local rows), P tf32-rounded at store
        const int ktm = kt % 3;
#pragma unroll
        for (int j = 0; j < 4; j++) {
            int c3 = (ktm + j * 8 + 2 * tig) % 3;
            int c3b = (c3 + 1 == 3) ? 0 : c3 + 1;
            float p0 = tfr(fexp(fmaf(sacc[j][0], 0.125f, pbs[qm0 * 3 + c3])));
            float p1 = tfr(fexp(fmaf(sacc[j][1], 0.125f, pbs[qm0 * 3 + c3b])));
            float p2 = tfr(fexp(fmaf(sacc[j][2], 0.125f, pbs[qm8 * 3 + c3])));
            float p3 = tfr(fexp(fmaf(sacc[j][3], 0.125f, pbs[qm8 * 3 + c3b])));
            lg += p0 + p1; lh += p2 + p3;
            *(float2*)&Pt[qrow * 36 + j * 8 + 2 * tig]       = make_float2(p0, p1);
            *(float2*)&Pt[(qrow + 8) * 36 + j * 8 + 2 * tig] = make_float2(p2, p3);
        }
        __syncwarp();

        // ctx += P V (1-pass tf32)
#pragma unroll
        for (int kk = 0; kk < 4; kk++) {
            uint32_t a0 = fbits(pbase[kk * 8]);
            uint32_t a1 = fbits(pbase[kk * 8 + 8 * 36]);
            uint32_t a2 = fbits(pbase[kk * 8 + 4]);
            uint32_t a3 = fbits(pbase[kk * 8 + 8 * 36 + 4]);
#pragma unroll
            for (int j = 0; j < 8; j++) {
                const float* vp = &Vt[(kk * 8 + tig) * 72 + j * 8 + g];
                mma8(cacc[j], a0, a1, a2, a3, fbits(vp[0]), fbits(vp[4 * 72]));
            }
        }
    }

    // row-sum reduce over the 4 lanes of each row group
    lg += __shfl_xor_sync(~0u, lg, 1); lg += __shfl_xor_sync(~0u, lg, 2);
    lh += __shfl_xor_sync(~0u, lh, 1); lh += __shfl_xor_sync(~0u, lh, 2);
    float ig = 1.f / lg, ih = 1.f / lh;

    size_t rb = (size_t)(b * T_SEQ + q0 + qrow) * C_DIM + h * DK;
#pragma unroll
    for (int j = 0; j < 8; j++) {
        int c = j * 8 + 2 * tig;
        *(float2*)&ctx[rb + c] = make_float2(cacc[j][0] * ig, cacc[j][1] * ig);
        *(float2*)&ctx[rb + 8 * C_DIM + c] = make_float2(cacc[j][2] * ih, cacc[j][3] * ih);
    }
}

// ---------------------------------------------------------------------------
// LayerNorm: one block (128 thr) per row of 512.
// ---------------------------------------------------------------------------
__global__ __launch_bounds__(128) void ln_kernel(
    const float* __restrict__ in, const float* __restrict__ g,
    const float* __restrict__ bta, float* __restrict__ out)
{
    __shared__ float r1[4], r2[4];
    const size_t rowb = (size_t)blockIdx.x * C_DIM;
    const int tid = threadIdx.x;

    float4 v = *(const float4*)&in[rowb + (tid << 2)];
    float s = v.x + v.y + v.z + v.w;
#pragma unroll
    for (int off = 16; off; off >>= 1) s += __shfl_xor_sync(~0u, s, off);
    if ((tid & 31) == 0) r1[tid >> 5] = s;
    __syncthreads();
    float mu = (r1[0] + r1[1] + r1[2] + r1[3]) * (1.f / C_DIM);

    float dx = v.x - mu, dy = v.y - mu, dz = v.z - mu, dw = v.w - mu;
    float ss = dx * dx + dy * dy + dz * dz + dw * dw;
#pragma unroll
    for (int off = 16; off; off >>= 1) ss += __shfl_xor_sync(~0u, ss, off);
    if ((tid & 31) == 0) r2[tid >> 5] = ss;
    __syncthreads();
    float inv = rsqrtf((r2[0] + r2[1] + r2[2] + r2[3]) * (1.f / C_DIM) + 1e-5f);

    float4 gg = *(const float4*)&g[tid << 2];
    float4 bb = *(const float4*)&bta[tid << 2];
    float4 o4;
    o4.x = dx * inv * gg.x + bb.x;
    o4.y = dy * inv * gg.y + bb.y;
    o4.z = dz * inv * gg.z + bb.z;
    o4.w = dw * inv * gg.w + bb.w;
    *(float4*)&out[rowb + (tid << 2)] = o4;
}

// ---------------------------------------------------------------------------
extern "C" void kernel_launch(void* const* d_in, const int* in_sizes, int n_in,
                              void* d_out, int out_size)
{
    const float* x  = (const float*)d_in[0];
    const float* Wq = (const float*)d_in[1];
    const float* bq = (const float*)d_in[2];
    const float* Wk = (const float*)d_in[3];
    const float* bk = (const float*)d_in[4];
    const float* Wv = (const float*)d_in[5];
    const float* bv = (const float*)d_in[6];
    const float* Wo = (const float*)d_in[7];
    const float* bo = (const float*)d_in[8];
    const float* pb = (const float*)d_in[9];
    const float* lg = (const float*)d_in[10];
    const float* lb = (const float*)d_in[11];
    float* out = (float*)d_out;

    float *q, *k, *v, *ctx, *y;
    cudaGetSymbolAddress((void**)&q,   g_Q);
    cudaGetSymbolAddress((void**)&k,   g_K);
    cudaGetSymbolAddress((void**)&v,   g_V);
    cudaGetSymbolAddress((void**)&ctx, g_CTX);
    cudaGetSymbolAddress((void**)&y,   g_Y);

    dim3 gg(C_DIM / 64, M_ROWS / 128);   // (8, 64)
    gemm_mma<<<gg, 256>>>(x, Wq, bq, nullptr, q);
    gemm_mma<<<gg, 256>>>(x, Wk, bk, nullptr, k);
    gemm_mma<<<gg, 256>>>(x, Wv, bv, nullptr, v);

    attn_mma<<<dim3(T_SEQ / 64, H_NUM, B_SZ), 128>>>(q, k, v, pb, ctx);

    gemm_mma<<<gg, 256>>>(ctx, Wo, bo, x, y);

    ln_kernel<<<M_ROWS, 128>>>(y, lg, lb, out);
}

// round 9
// speedup vs baseline: 6.5929x; 1.4350x over previous
#include <cuda_runtime.h>
#include <cstdint>

#define C_DIM 512
#define T_SEQ 2048
#define B_SZ 4
#define H_NUM 8
#define DK 64
#define M_ROWS (B_SZ * T_SEQ)   // 8192

__device__ float g_Q[M_ROWS * C_DIM];
__device__ float g_K[M_ROWS * C_DIM];
__device__ float g_V[M_ROWS * C_DIM];
__device__ float g_CTX[M_ROWS * C_DIM];
__device__ float g_Y[M_ROWS * C_DIM];

// ---------------------------------------------------------------------------
// helpers
// ---------------------------------------------------------------------------
__device__ __forceinline__ uint32_t f2tf(float x) {
    uint32_t r; asm("cvt.rna.tf32.f32 %0, %1;" : "=r"(r) : "f"(x)); return r;
}
__device__ __forceinline__ float tfr(float x) {
    return __uint_as_float(f2tf(x));
}
__device__ __forceinline__ uint32_t fbits(float x) { return __float_as_uint(x); }

// pack two floats -> bf16x2 (lo = e, hi = o)
__device__ __forceinline__ uint32_t pk2(float e, float o) {
    uint32_t d;
    asm("cvt.rn.bf16x2.f32 %0, %1, %2;" : "=r"(d) : "f"(o), "f"(e));
    return d;
}

// tf32 m16n8k8
__device__ __forceinline__ void mma8(float* c,
    uint32_t a0, uint32_t a1, uint32_t a2, uint32_t a3,
    uint32_t b0, uint32_t b1)
{
    asm volatile(
        "mma.sync.aligned.m16n8k8.row.col.f32.tf32.tf32.f32 "
        "{%0,%1,%2,%3}, {%4,%5,%6,%7}, {%8,%9}, {%0,%1,%2,%3};"
        : "+f"(c[0]), "+f"(c[1]), "+f"(c[2]), "+f"(c[3])
        : "r"(a0), "r"(a1), "r"(a2), "r"(a3), "r"(b0), "r"(b1));
}
// bf16 m16n8k16
__device__ __forceinline__ void mma16(float* c,
    uint32_t a0, uint32_t a1, uint32_t a2, uint32_t a3,
    uint32_t b0, uint32_t b1)
{
    asm volatile(
        "mma.sync.aligned.m16n8k16.row.col.f32.bf16.bf16.f32 "
        "{%0,%1,%2,%3}, {%4,%5,%6,%7}, {%8,%9}, {%0,%1,%2,%3};"
        : "+f"(c[0]), "+f"(c[1]), "+f"(c[2]), "+f"(c[3])
        : "r"(a0), "r"(a1), "r"(a2), "r"(a3), "r"(b0), "r"(b1));
}

// FFMA-only exp; args bounded (|x| <~ 16)
__device__ __forceinline__ float fexp(float x) {
    const float L2E = 1.4426950408889634f;
    float t  = fmaf(x, L2E, 12582912.0f);
    float tn = t - 12582912.0f;
    float f  = fmaf(x, L2E, -tn);
    uint32_t sc = (__float_as_uint(t) << 23) + 0x3F800000u;
    float p = fmaf(f, 0.0013333558f, 0.0096181291f);
    p = fmaf(f, p, 0.0555041087f);
    p = fmaf(f, p, 0.2402265069f);
    p = fmaf(f, p, 0.6931471806f);
    p = fmaf(f, p, 1.0f);
    return p * __uint_as_float(sc);
}

// ---------------------------------------------------------------------------
// bf16 hi/lo 3-pass GEMM (k16 mma), BK=16, double-buffered + reg prefetch,
// one barrier per chunk.  out = A*W^T + bias (+res).  Tile 128x64, 8 warps.
// Smem: (Ah+Al) 2buf*128*12 u32 + (Wh+Wl) 2buf*64*12 u32 = 36864 B.
// ---------------------------------------------------------------------------
__global__ __launch_bounds__(256, 2) void gemm_mma(
    const float* __restrict__ A, const float* __restrict__ W,
    const float* __restrict__ bias, const float* __restrict__ res,
    float* __restrict__ out)
{
    __shared__ __align__(16) uint32_t Ah[2][128 * 12], Al[2][128 * 12];
    __shared__ __align__(16) uint32_t Wh[2][64 * 12],  Wl[2][64 * 12];
    const int tid = threadIdx.x, w = tid >> 5, lid = tid & 31;
    const int g = lid >> 2, tig = lid & 3;
    const int wm = w & 3, wn = w >> 2;
    const int bm = blockIdx.y * 128, bn = blockIdx.x * 64;
    const int lr = tid >> 2, lc = (tid & 3) << 2;

    float acc[2][4][4] = {};

    // prefetch chunk 0
    float4 ar[2], wr;
    ar[0] = *(const float4*)(A + (size_t)(bm + lr) * C_DIM + lc);
    ar[1] = *(const float4*)(A + (size_t)(bm + 64 + lr) * C_DIM + lc);
    wr    = *(const float4*)(W + (size_t)(bn + lr) * C_DIM + lc);

    for (int c = 0; c < 32; c++) {
        const int buf = c & 1;
        // hi/lo split + STS
#pragma unroll
        for (int it = 0; it < 2; it++) {
            float4 v = ar[it];
            uint32_t h0 = pk2(v.x, v.y), h1 = pk2(v.z, v.w);
            float e0 = __uint_as_float(h0 << 16), o0 = __uint_as_float(h0 & 0xffff0000u);
            float e1 = __uint_as_float(h1 << 16), o1 = __uint_as_float(h1 & 0xffff0000u);
            uint32_t l0 = pk2(v.x - e0, v.y - o0), l1 = pk2(v.z - e1, v.w - o1);
            int r = lr + it * 64, cc = (tid & 3) << 1;
            *(uint2*)&Ah[buf][r * 12 + cc] = make_uint2(h0, h1);
            *(uint2*)&Al[buf][r * 12 + cc] = make_uint2(l0, l1);
        }
        {
            float4 v = wr;
            uint32_t h0 = pk2(v.x, v.y), h1 = pk2(v.z, v.w);
            float e0 = __uint_as_float(h0 << 16), o0 = __uint_as_float(h0 & 0xffff0000u);
            float e1 = __uint_as_float(h1 << 16), o1 = __uint_as_float(h1 & 0xffff0000u);
            uint32_t l0 = pk2(v.x - e0, v.y - o0), l1 = pk2(v.z - e1, v.w - o1);
            int cc = (tid & 3) << 1;
            *(uint2*)&Wh[buf][lr * 12 + cc] = make_uint2(h0, h1);
            *(uint2*)&Wl[buf][lr * 12 + cc] = make_uint2(l0, l1);
        }
        if (c < 31) {
            int k0 = (c + 1) * 16;
            ar[0] = *(const float4*)(A + (size_t)(bm + lr) * C_DIM + k0 + lc);
            ar[1] = *(const float4*)(A + (size_t)(bm + 64 + lr) * C_DIM + k0 + lc);
            wr    = *(const float4*)(W + (size_t)(bn + lr) * C_DIM + k0 + lc);
        }
        __syncthreads();

        uint32_t ah[2][4], al[2][4];
#pragma unroll
        for (int i = 0; i < 2; i++) {
            int ro = (wm * 32 + i * 16 + g) * 12 + tig;
            ah[i][0] = Ah[buf][ro];       al[i][0] = Al[buf][ro];
            ah[i][1] = Ah[buf][ro + 96];  al[i][1] = Al[buf][ro + 96];
            ah[i][2] = Ah[buf][ro + 4];   al[i][2] = Al[buf][ro + 4];
            ah[i][3] = Ah[buf][ro + 100]; al[i][3] = Al[buf][ro + 100];
        }
#pragma unroll
        for (int j = 0; j < 4; j++) {
            int co = (wn * 32 + j * 8 + g) * 12 + tig;
            uint32_t bh0 = Wh[buf][co], bh1 = Wh[buf][co + 4];
            uint32_t bl0 = Wl[buf][co], bl1 = Wl[buf][co + 4];
#pragma unroll
            for (int i = 0; i < 2; i++) {
                mma16(acc[i][j], ah[i][0], ah[i][1], ah[i][2], ah[i][3], bh0, bh1);
                mma16(acc[i][j], ah[i][0], ah[i][1], ah[i][2], ah[i][3], bl0, bl1);
                mma16(acc[i][j], al[i][0], al[i][1], al[i][2], al[i][3], bh0, bh1);
            }
        }
    }

#pragma unroll
    for (int i = 0; i < 2; i++) {
#pragma unroll
        for (int j = 0; j < 4; j++) {
            int r0 = bm + wm * 32 + i * 16 + g;
            int cc = bn + wn * 32 + j * 8 + 2 * tig;
            float2 bb = *(const float2*)&bias[cc];
            float2 o0 = make_float2(acc[i][j][0] + bb.x, acc[i][j][1] + bb.y);
            float2 o1 = make_float2(acc[i][j][2] + bb.x, acc[i][j][3] + bb.y);
            if (res) {
                float2 ra = *(const float2*)&res[(size_t)r0 * C_DIM + cc];
                float2 rb = *(const float2*)&res[(size_t)(r0 + 8) * C_DIM + cc];
                o0.x += ra.x; o0.y += ra.y; o1.x += rb.x; o1.y += rb.y;
            }
            *(float2*)&out[(size_t)r0 * C_DIM + cc] = o0;
            *(float2*)&out[(size_t)(r0 + 8) * C_DIM + cc] = o1;
        }
    }
}

// ---------------------------------------------------------------------------
// Attention: S = bf16 k16 mma (Q frags in regs), PV = tf32 k8 (as R8).
// Double-buffered K/V smem, reg prefetch, 1 barrier/tile.
// CTA = (b,h,64 q); 4 warps x 16 rows; 64 key tiles of 32.
// Smem: Kb 2x32x36 u32 (9216) + Vs 2x32x72 f32 (18432) + Pt 64x36 f32 (9216).
// ---------------------------------------------------------------------------
__global__ __launch_bounds__(128, 4) void attn_mma(
    const float* __restrict__ Qg, const float* __restrict__ Kg,
    const float* __restrict__ Vg, const float* __restrict__ pb,
    float* __restrict__ ctx)
{
    __shared__ __align__(16) uint32_t Kb[2][32 * 36];
    __shared__ __align__(16) float Vs[2][32 * 72];
    __shared__ __align__(8)  float Pt[64 * 36];
    __shared__ float pbs[9];

    const int tid = threadIdx.x, w = tid >> 5, lid = tid & 31;
    const int g = lid >> 2, tig = lid & 3;
    const int h = blockIdx.y, b = blockIdx.z, q0 = blockIdx.x * 64;

    if (tid < 9) pbs[tid] = pb[tid];

    // prefetch K/V tile 0 (latency covered by Q staging below)
    float4 kreg[4], vreg[4];
#pragma unroll
    for (int it = 0; it < 4; it++) {
        int f = tid + it * 128, r = f >> 4, c4 = (f & 15) << 2;
        size_t gi = (size_t)(b * T_SEQ + r) * C_DIM + h * DK + c4;
        kreg[it] = *(const float4*)(Kg + gi);
        vreg[it] = *(const float4*)(Vg + gi);
    }

    // stage Q (64x64) as bf16x2 through the two Kb buffers
#pragma unroll
    for (int it = 0; it < 8; it++) {
        int f = tid + it * 128, r = f >> 4, c4 = (f & 15) << 2;
        float4 v = *(const float4*)(Qg + (size_t)(b * T_SEQ + q0 + r) * C_DIM + h * DK + c4);
        *(uint2*)&Kb[r >> 5][(r & 31) * 36 + (c4 >> 1)] =
            make_uint2(pk2(v.x, v.y), pk2(v.z, v.w));
    }
    __syncthreads();

    const int qrow = 16 * w + g;
    uint32_t qf[4][4];
    {
        const uint32_t* Qb = Kb[qrow >> 5];
        int r0 = (qrow & 31) * 36, r1 = ((qrow + 8) & 31) * 36;
#pragma unroll
        for (int kk = 0; kk < 4; kk++) {
            qf[kk][0] = Qb[r0 + kk * 8 + tig];
            qf[kk][1] = Qb[r1 + kk * 8 + tig];
            qf[kk][2] = Qb[r0 + kk * 8 + tig + 4];
            qf[kk][3] = Qb[r1 + kk * 8 + tig + 4];
        }
    }
    __syncthreads();   // Q frag reads done before Kb reuse

    const int qm0 = (q0 + qrow) % 3, qm8 = (qm0 + 2) % 3;
    const float* pbase = &Pt[qrow * 36 + tig];
    float cacc[8][4] = {};
    float lg = 0.f, lh = 0.f;

    for (int t = 0; t < 64; t++) {
        const int buf = t & 1, kt = t * 32;

        // store current tile (bf16 K, tf32-rounded V)
#pragma unroll
        for (int it = 0; it < 4; it++) {
            int f = tid + it * 128, r = f >> 4, c4 = (f & 15) << 2;
            float4 kv = kreg[it], vv = vreg[it];
            *(uint2*)&Kb[buf][r * 36 + (c4 >> 1)] =
                make_uint2(pk2(kv.x, kv.y), pk2(kv.z, kv.w));
            *(float4*)&Vs[buf][r * 72 + c4] =
                make_float4(tfr(vv.x), tfr(vv.y), tfr(vv.z), tfr(vv.w));
        }
        // prefetch next K (hidden under this tile's MMA work)
        if (t < 63) {
#pragma unroll
            for (int it = 0; it < 4; it++) {
                int f = tid + it * 128, r = f >> 4, c4 = (f & 15) << 2;
                kreg[it] = *(const float4*)(Kg +
                    (size_t)(b * T_SEQ + kt + 32 + r) * C_DIM + h * DK + c4);
            }
        }
        __syncthreads();

        // S = Q K^T  (bf16 k16: 16 mma)
        float sacc[4][4] = {};
#pragma unroll
        for (int kk = 0; kk < 4; kk++) {
#pragma unroll
            for (int j = 0; j < 4; j++) {
                const uint32_t* kp = &Kb[buf][(j * 8 + g) * 36 + kk * 8 + tig];
                mma16(sacc[j], qf[kk][0], qf[kk][1], qf[kk][2], qf[kk][3],
                      kp[0], kp[4]);
            }
        }

        // prefetch next V (hidden under softmax + PV)
        if (t < 63) {
#pragma unroll
            for (int it = 0; it < 4; it++) {
                int f = tid + it * 128, r = f >> 4, c4 = (f & 15) << 2;
                vreg[it] = *(const float4*)(Vg +
                    (size_t)(b * T_SEQ + kt + 32 + r) * C_DIM + h * DK + c4);
            }
        }

        // softmax + P store (warp-local rows)
        const int ktm = kt % 3;
#pragma unroll
        for (int j = 0; j < 4; j++) {
            int c3 = (ktm + j * 8 + 2 * tig) % 3;
            int c3b = (c3 + 1 == 3) ? 0 : c3 + 1;
            float p0 = tfr(fexp(fmaf(sacc[j][0], 0.125f, pbs[qm0 * 3 + c3])));
            float p1 = tfr(fexp(fmaf(sacc[j][1], 0.125f, pbs[qm0 * 3 + c3b])));
            float p2 = tfr(fexp(fmaf(sacc[j][2], 0.125f, pbs[qm8 * 3 + c3])));
            float p3 = tfr(fexp(fmaf(sacc[j][3], 0.125f, pbs[qm8 * 3 + c3b])));
            lg += p0 + p1; lh += p2 + p3;
            *(float2*)&Pt[qrow * 36 + j * 8 + 2 * tig]       = make_float2(p0, p1);
            *(float2*)&Pt[(qrow + 8) * 36 + j * 8 + 2 * tig] = make_float2(p2, p3);
        }
        __syncwarp();

        // ctx += P V  (tf32 k8)
#pragma unroll
        for (int kk = 0; kk < 4; kk++) {
            uint32_t a0 = fbits(pbase[kk * 8]);
            uint32_t a1 = fbits(pbase[kk * 8 + 8 * 36]);
            uint32_t a2 = fbits(pbase[kk * 8 + 4]);
            uint32_t a3 = fbits(pbase[kk * 8 + 8 * 36 + 4]);
#pragma unroll
            for (int j = 0; j < 8; j++) {
                const float* vp = &Vs[buf][(kk * 8 + tig) * 72 + j * 8 + g];
                mma8(cacc[j], a0, a1, a2, a3, fbits(vp[0]), fbits(vp[4 * 72]));
            }
        }
    }

    lg += __shfl_xor_sync(~0u, lg, 1); lg += __shfl_xor_sync(~0u, lg, 2);
    lh += __shfl_xor_sync(~0u, lh, 1); lh += __shfl_xor_sync(~0u, lh, 2);
    float ig = 1.f / lg, ih = 1.f / lh;

    size_t rb = (size_t)(b * T_SEQ + q0 + qrow) * C_DIM + h * DK;
#pragma unroll
    for (int j = 0; j < 8; j++) {
        int c = j * 8 + 2 * tig;
        *(float2*)&ctx[rb + c] = make_float2(cacc[j][0] * ig, cacc[j][1] * ig);
        *(float2*)&ctx[rb + 8 * C_DIM + c] = make_float2(cacc[j][2] * ih, cacc[j][3] * ih);
    }
}

// ---------------------------------------------------------------------------
// LayerNorm: one block (128 thr) per row of 512.
// ---------------------------------------------------------------------------
__global__ __launch_bounds__(128) void ln_kernel(
    const float* __restrict__ in, const float* __restrict__ g,
    const float* __restrict__ bta, float* __restrict__ out)
{
    __shared__ float r1[4], r2[4];
    const size_t rowb = (size_t)blockIdx.x * C_DIM;
    const int tid = threadIdx.x;

    float4 v = *(const float4*)&in[rowb + (tid << 2)];
    float s = v.x + v.y + v.z + v.w;
#pragma unroll
    for (int off = 16; off; off >>= 1) s += __shfl_xor_sync(~0u, s, off);
    if ((tid & 31) == 0) r1[tid >> 5] = s;
    __syncthreads();
    float mu = (r1[0] + r1[1] + r1[2] + r1[3]) * (1.f / C_DIM);

    float dx = v.x - mu, dy = v.y - mu, dz = v.z - mu, dw = v.w - mu;
    float ss = dx * dx + dy * dy + dz * dz + dw * dw;
#pragma unroll
    for (int off = 16; off; off >>= 1) ss += __shfl_xor_sync(~0u, ss, off);
    if ((tid & 31) == 0) r2[tid >> 5] = ss;
    __syncthreads();
    float inv = rsqrtf((r2[0] + r2[1] + r2[2] + r2[3]) * (1.f / C_DIM) + 1e-5f);

    float4 gg = *(const float4*)&g[tid << 2];
    float4 bb = *(const float4*)&bta[tid << 2];
    float4 o4;
    o4.x = dx * inv * gg.x + bb.x;
    o4.y = dy * inv * gg.y + bb.y;
    o4.z = dz * inv * gg.z + bb.z;
    o4.w = dw * inv * gg.w + bb.w;
    *(float4*)&out[rowb + (tid << 2)] = o4;
}

// ---------------------------------------------------------------------------
extern "C" void kernel_launch(void* const* d_in, const int* in_sizes, int n_in,
                              void* d_out, int out_size)
{
    const float* x  = (const float*)d_in[0];
    const float* Wq = (const float*)d_in[1];
    const float* bq = (const float*)d_in[2];
    const float* Wk = (const float*)d_in[3];
    const float* bk = (const float*)d_in[4];
    const float* Wv = (const float*)d_in[5];
    const float* bv = (const float*)d_in[6];
    const float* Wo = (const float*)d_in[7];
    const float* bo = (const float*)d_in[8];
    const float* pb = (const float*)d_in[9];
    const float* lg = (const float*)d_in[10];
    const float* lb = (const float*)d_in[11];
    float* out = (float*)d_out;

    float *q, *k, *v, *ctx, *y;
    cudaGetSymbolAddress((void**)&q,   g_Q);
    cudaGetSymbolAddress((void**)&k,   g_K);
    cudaGetSymbolAddress((void**)&v,   g_V);
    cudaGetSymbolAddress((void**)&ctx, g_CTX);
    cudaGetSymbolAddress((void**)&y,   g_Y);

    dim3 gg(C_DIM / 64, M_ROWS / 128);   // (8, 64)
    gemm_mma<<<gg, 256>>>(x, Wq, bq, nullptr, q);
    gemm_mma<<<gg, 256>>>(x, Wk, bk, nullptr, k);
    gemm_mma<<<gg, 256>>>(x, Wv, bv, nullptr, v);

    attn_mma<<<dim3(T_SEQ / 64, H_NUM, B_SZ), 128>>>(q, k, v, pb, ctx);

    gemm_mma<<<gg, 256>>>(ctx, Wo, bo, x, y);

    ln_kernel<<<M_ROWS, 128>>>(y, lg, lb, out);
}

// round 10
// speedup vs baseline: 7.5789x; 1.1496x over previous
#include <cuda_runtime.h>
#include <cstdint>

#define C_DIM 512
#define T_SEQ 2048
#define B_SZ 4
#define H_NUM 8
#define DK 64
#define M_ROWS (B_SZ * T_SEQ)   // 8192

__device__ uint32_t g_Qb[M_ROWS * (C_DIM / 2)];   // bf16x2 packed Q
__device__ uint32_t g_Kb[M_ROWS * (C_DIM / 2)];   // bf16x2 packed K
__device__ float    g_V  [M_ROWS * C_DIM];        // tf32-rounded V
__device__ float    g_CTX[M_ROWS * C_DIM];
__device__ float    g_Y  [M_ROWS * C_DIM];

// ---------------------------------------------------------------------------
// helpers
// ---------------------------------------------------------------------------
__device__ __forceinline__ uint32_t f2tf(float x) {
    uint32_t r; asm("cvt.rna.tf32.f32 %0, %1;" : "=r"(r) : "f"(x)); return r;
}
__device__ __forceinline__ float tfr(float x) { return __uint_as_float(f2tf(x)); }
__device__ __forceinline__ uint32_t fbits(float x) { return __float_as_uint(x); }
__device__ __forceinline__ uint32_t pk2(float e, float o) {
    uint32_t d;
    asm("cvt.rn.bf16x2.f32 %0, %1, %2;" : "=r"(d) : "f"(o), "f"(e));
    return d;
}
__device__ __forceinline__ uint32_t sptr(const void* p) {
    return (uint32_t)__cvta_generic_to_shared(p);
}
#define CP16(sa, ga) asm volatile("cp.async.cg.shared.global [%0], [%1], 16;" :: "r"(sa), "l"(ga))
#define CP_COMMIT()  asm volatile("cp.async.commit_group;" ::: "memory")
#define CP_WAIT0()   asm volatile("cp.async.wait_group 0;" ::: "memory")

// tf32 m16n8k8
__device__ __forceinline__ void mma8(float* c,
    uint32_t a0, uint32_t a1, uint32_t a2, uint32_t a3, uint32_t b0, uint32_t b1)
{
    asm volatile(
        "mma.sync.aligned.m16n8k8.row.col.f32.tf32.tf32.f32 "
        "{%0,%1,%2,%3}, {%4,%5,%6,%7}, {%8,%9}, {%0,%1,%2,%3};"
        : "+f"(c[0]), "+f"(c[1]), "+f"(c[2]), "+f"(c[3])
        : "r"(a0), "r"(a1), "r"(a2), "r"(a3), "r"(b0), "r"(b1));
}
// bf16 m16n8k16
__device__ __forceinline__ void mma16(float* c,
    uint32_t a0, uint32_t a1, uint32_t a2, uint32_t a3, uint32_t b0, uint32_t b1)
{
    asm volatile(
        "mma.sync.aligned.m16n8k16.row.col.f32.bf16.bf16.f32 "
        "{%0,%1,%2,%3}, {%4,%5,%6,%7}, {%8,%9}, {%0,%1,%2,%3};"
        : "+f"(c[0]), "+f"(c[1]), "+f"(c[2]), "+f"(c[3])
        : "r"(a0), "r"(a1), "r"(a2), "r"(a3), "r"(b0), "r"(b1));
}

// FFMA-only exp; args bounded (|x| <~ 16)
__device__ __forceinline__ float fexp(float x) {
    const float L2E = 1.4426950408889634f;
    float t  = fmaf(x, L2E, 12582912.0f);
    float tn = t - 12582912.0f;
    float f  = fmaf(x, L2E, -tn);
    uint32_t sc = (__float_as_uint(t) << 23) + 0x3F800000u;
    float p = fmaf(f, 0.0013333558f, 0.0096181291f);
    p = fmaf(f, p, 0.0555041087f);
    p = fmaf(f, p, 0.2402265069f);
    p = fmaf(f, p, 0.6931471806f);
    p = fmaf(f, p, 1.0f);
    return p * __uint_as_float(sc);
}

// ===========================================================================
// GEMM mainloop (bf16 hi/lo 3-pass, k16, double buffered) — shared via macro-
// style inline: computes acc[2][4][4] for tile (bm, bn) of A*W^T.
// ===========================================================================
struct GemmCore {
    __device__ static void run(const float* A, const float* W, int bm, int bn,
                               float acc[2][4][4],
                               uint32_t (*Ah)[128 * 12], uint32_t (*Al)[128 * 12],
                               uint32_t (*Wh)[64 * 12],  uint32_t (*Wl)[64 * 12],
                               int tid)
    {
        const int w = tid >> 5, lid = tid & 31;
        const int g = lid >> 2, tig = lid & 3;
        const int wm = w & 3, wn = w >> 2;
        const int lr = tid >> 2, lc = (tid & 3) << 2;

        float4 ar[2], wr;
        ar[0] = *(const float4*)(A + (size_t)(bm + lr) * C_DIM + lc);
        ar[1] = *(const float4*)(A + (size_t)(bm + 64 + lr) * C_DIM + lc);
        wr    = *(const float4*)(W + (size_t)(bn + lr) * C_DIM + lc);

        for (int c = 0; c < 32; c++) {
            const int buf = c & 1;
#pragma unroll
            for (int it = 0; it < 2; it++) {
                float4 v = ar[it];
                uint32_t h0 = pk2(v.x, v.y), h1 = pk2(v.z, v.w);
                float e0 = __uint_as_float(h0 << 16), o0 = __uint_as_float(h0 & 0xffff0000u);
                float e1 = __uint_as_float(h1 << 16), o1 = __uint_as_float(h1 & 0xffff0000u);
                uint32_t l0 = pk2(v.x - e0, v.y - o0), l1 = pk2(v.z - e1, v.w - o1);
                int r = lr + it * 64, cc = (tid & 3) << 1;
                *(uint2*)&Ah[buf][r * 12 + cc] = make_uint2(h0, h1);
                *(uint2*)&Al[buf][r * 12 + cc] = make_uint2(l0, l1);
            }
            {
                float4 v = wr;
                uint32_t h0 = pk2(v.x, v.y), h1 = pk2(v.z, v.w);
                float e0 = __uint_as_float(h0 << 16), o0 = __uint_as_float(h0 & 0xffff0000u);
                float e1 = __uint_as_float(h1 << 16), o1 = __uint_as_float(h1 & 0xffff0000u);
                uint32_t l0 = pk2(v.x - e0, v.y - o0), l1 = pk2(v.z - e1, v.w - o1);
                int cc = (tid & 3) << 1;
                *(uint2*)&Wh[buf][lr * 12 + cc] = make_uint2(h0, h1);
                *(uint2*)&Wl[buf][lr * 12 + cc] = make_uint2(l0, l1);
            }
            if (c < 31) {
                int k0 = (c + 1) * 16;
                ar[0] = *(const float4*)(A + (size_t)(bm + lr) * C_DIM + k0 + lc);
                ar[1] = *(const float4*)(A + (size_t)(bm + 64 + lr) * C_DIM + k0 + lc);
                wr    = *(const float4*)(W + (size_t)(bn + lr) * C_DIM + k0 + lc);
            }
            __syncthreads();

            uint32_t ah[2][4], al[2][4];
#pragma unroll
            for (int i = 0; i < 2; i++) {
                int ro = (wm * 32 + i * 16 + g) * 12 + tig;
                ah[i][0] = Ah[buf][ro];       al[i][0] = Al[buf][ro];
                ah[i][1] = Ah[buf][ro + 96];  al[i][1] = Al[buf][ro + 96];
                ah[i][2] = Ah[buf][ro + 4];   al[i][2] = Al[buf][ro + 4];
                ah[i][3] = Ah[buf][ro + 100]; al[i][3] = Al[buf][ro + 100];
            }
#pragma unroll
            for (int j = 0; j < 4; j++) {
                int co = (wn * 32 + j * 8 + g) * 12 + tig;
                uint32_t bh0 = Wh[buf][co], bh1 = Wh[buf][co + 4];
                uint32_t bl0 = Wl[buf][co], bl1 = Wl[buf][co + 4];
#pragma unroll
                for (int i = 0; i < 2; i++) {
                    mma16(acc[i][j], ah[i][0], ah[i][1], ah[i][2], ah[i][3], bh0, bh1);
                    mma16(acc[i][j], ah[i][0], ah[i][1], ah[i][2], ah[i][3], bl0, bl1);
                    mma16(acc[i][j], al[i][0], al[i][1], al[i][2], al[i][3], bh0, bh1);
                }
            }
        }
    }
};

// ---------------------------------------------------------------------------
// Fused QKV projection: grid (24, 64); proj = bx>>3 selects W/bias/output.
// proj 0/1 -> packed bf16x2 (g_Qb/g_Kb); proj 2 -> tf32-rounded fp32 (g_V).
// ---------------------------------------------------------------------------
__global__ __launch_bounds__(256, 2) void qkv_gemm(
    const float* __restrict__ x,
    const float* __restrict__ Wq, const float* __restrict__ bq,
    const float* __restrict__ Wk, const float* __restrict__ bk,
    const float* __restrict__ Wv, const float* __restrict__ bv,
    uint32_t* __restrict__ Qb, uint32_t* __restrict__ Kb,
    float* __restrict__ Vout)
{
    __shared__ __align__(16) uint32_t Ah[2][128 * 12], Al[2][128 * 12];
    __shared__ __align__(16) uint32_t Wh[2][64 * 12],  Wl[2][64 * 12];
    const int tid = threadIdx.x, w = tid >> 5, lid = tid & 31;
    const int g = lid >> 2, tig = lid & 3;
    const int wm = w & 3, wn = w >> 2;
    const int proj = blockIdx.x >> 3;
    const int bm = blockIdx.y * 128, bn = (blockIdx.x & 7) * 64;

    const float* W  = (proj == 0) ? Wq : (proj == 1) ? Wk : Wv;
    const float* bs = (proj == 0) ? bq : (proj == 1) ? bk : bv;

    float acc[2][4][4] = {};
    GemmCore::run(x, W, bm, bn, acc, Ah, Al, Wh, Wl, tid);

#pragma unroll
    for (int i = 0; i < 2; i++) {
#pragma unroll
        for (int j = 0; j < 4; j++) {
            int r0 = bm + wm * 32 + i * 16 + g;
            int cc = bn + wn * 32 + j * 8 + 2 * tig;
            float2 bb = *(const float2*)&bs[cc];
            float2 o0 = make_float2(acc[i][j][0] + bb.x, acc[i][j][1] + bb.y);
            float2 o1 = make_float2(acc[i][j][2] + bb.x, acc[i][j][3] + bb.y);
            if (proj == 2) {
                *(float2*)&Vout[(size_t)r0 * C_DIM + cc] =
                    make_float2(tfr(o0.x), tfr(o0.y));
                *(float2*)&Vout[(size_t)(r0 + 8) * C_DIM + cc] =
                    make_float2(tfr(o1.x), tfr(o1.y));
            } else {
                uint32_t* ob = (proj == 0) ? Qb : Kb;
                ob[(size_t)r0 * 256 + (cc >> 1)]       = pk2(o0.x, o0.y);
                ob[(size_t)(r0 + 8) * 256 + (cc >> 1)] = pk2(o1.x, o1.y);
            }
        }
    }
}

// ---------------------------------------------------------------------------
// Output projection: fp32 out = ctx*Wo^T + bias + residual.
// ---------------------------------------------------------------------------
__global__ __launch_bounds__(256, 2) void wo_gemm(
    const float* __restrict__ A, const float* __restrict__ W,
    const float* __restrict__ bias, const float* __restrict__ res,
    float* __restrict__ out)
{
    __shared__ __align__(16) uint32_t Ah[2][128 * 12], Al[2][128 * 12];
    __shared__ __align__(16) uint32_t Wh[2][64 * 12],  Wl[2][64 * 12];
    const int tid = threadIdx.x, w = tid >> 5, lid = tid & 31;
    const int g = lid >> 2, tig = lid & 3;
    const int wm = w & 3, wn = w >> 2;
    const int bm = blockIdx.y * 128, bn = blockIdx.x * 64;

    float acc[2][4][4] = {};
    GemmCore::run(A, W, bm, bn, acc, Ah, Al, Wh, Wl, tid);

#pragma unroll
    for (int i = 0; i < 2; i++) {
#pragma unroll
        for (int j = 0; j < 4; j++) {
            int r0 = bm + wm * 32 + i * 16 + g;
            int cc = bn + wn * 32 + j * 8 + 2 * tig;
            float2 bb = *(const float2*)&bias[cc];
            float2 ra = *(const float2*)&res[(size_t)r0 * C_DIM + cc];
            float2 rb = *(const float2*)&res[(size_t)(r0 + 8) * C_DIM + cc];
            *(float2*)&out[(size_t)r0 * C_DIM + cc] =
                make_float2(acc[i][j][0] + bb.x + ra.x, acc[i][j][1] + bb.y + ra.y);
            *(float2*)&out[(size_t)(r0 + 8) * C_DIM + cc] =
                make_float2(acc[i][j][2] + bb.x + rb.x, acc[i][j][3] + bb.y + rb.y);
        }
    }
}

// ---------------------------------------------------------------------------
// Attention: Q/K pre-packed bf16 (S: k16 mma), V pre-rounded tf32 (PV: k8).
// cp.async double-buffered K/V, 1 barrier/tile, no in-loop conversions.
// CTA = (b,h,64 q); 4 warps x 16 rows; 64 key tiles of 32.
// Smem: Ks 2x32x36 u32 (9216) + Vsm 2x32x72 f32 (18432) + Pt 64x36 (9216).
// ---------------------------------------------------------------------------
__global__ __launch_bounds__(128, 5) void attn_mma(
    const uint32_t* __restrict__ Qb, const uint32_t* __restrict__ Kbg,
    const float* __restrict__ Vg, const float* __restrict__ pb,
    float* __restrict__ ctx)
{
    __shared__ __align__(16) uint32_t Ks[2][32 * 36];
    __shared__ __align__(16) float Vsm[2][32 * 72];
    __shared__ __align__(8)  float Pt[64 * 36];
    __shared__ float pbs[9];

    const int tid = threadIdx.x, w = tid >> 5, lid = tid & 31;
    const int g = lid >> 2, tig = lid & 3;
    const int h = blockIdx.y, b = blockIdx.z, q0 = blockIdx.x * 64;
    const size_t bT = (size_t)b * T_SEQ;

    if (tid < 9) pbs[tid] = pb[tid];

    // Q fragments via direct LDG (bf16x2 packed), one-time
    const int qrow = 16 * w + g;
    uint32_t qf[4][4];
    {
        const uint32_t* qp = Qb + (bT + q0 + qrow) * 256 + h * 32;
#pragma unroll
        for (int kk = 0; kk < 4; kk++) {
            qf[kk][0] = qp[kk * 8 + tig];
            qf[kk][1] = qp[8 * 256 + kk * 8 + tig];
            qf[kk][2] = qp[kk * 8 + tig + 4];
            qf[kk][3] = qp[8 * 256 + kk * 8 + tig + 4];
        }
    }

    // cp.async issue for one K/V tile into buffer `buf`
    auto issue = [&](int kt, int buf) {
        // K: 32 rows x 128B = 256 chunks of 16B; 2 per thread
#pragma unroll
        for (int i = 0; i < 2; i++) {
            int idx = tid + i * 128, r = idx >> 3, c = idx & 7;
            const uint32_t* ga = Kbg + (bT + kt + r) * 256 + h * 32 + c * 4;
            CP16(sptr(&Ks[buf][r * 36 + c * 4]), ga);
        }
        // V: 32 rows x 256B = 512 chunks; 4 per thread
#pragma unroll
        for (int i = 0; i < 4; i++) {
            int idx = tid + i * 128, r = idx >> 4, c = idx & 15;
            const float* ga = Vg + (bT + kt + r) * C_DIM + h * DK + c * 4;
            CP16(sptr(&Vsm[buf][r * 72 + c * 4]), ga);
        }
    };

    issue(0, 0);
    CP_COMMIT();

    const int qm0 = (q0 + qrow) % 3, qm8 = (qm0 + 2) % 3;
    const float* pbase = &Pt[qrow * 36 + tig];
    float cacc[8][4] = {};
    float lg = 0.f, lh = 0.f;

    for (int t = 0; t < 64; t++) {
        const int buf = t & 1, kt = t * 32;

        CP_WAIT0();
        __syncthreads();           // tile t ready; all warps done with buf^1
        if (t < 63) {
            issue(kt + 32, buf ^ 1);
            CP_COMMIT();
        }

        // S = Q K^T (bf16 k16)
        float sacc[4][4] = {};
#pragma unroll
        for (int kk = 0; kk < 4; kk++) {
#pragma unroll
            for (int j = 0; j < 4; j++) {
                const uint32_t* kp = &Ks[buf][(j * 8 + g) * 36 + kk * 8 + tig];
                mma16(sacc[j], qf[kk][0], qf[kk][1], qf[kk][2], qf[kk][3],
                      kp[0], kp[4]);
            }
        }

        // softmax + P store (warp-local rows)
        const int ktm = kt % 3;
#pragma unroll
        for (int j = 0; j < 4; j++) {
            int c3 = (ktm + j * 8 + 2 * tig) % 3;
            int c3b = (c3 + 1 == 3) ? 0 : c3 + 1;
            float p0 = tfr(fexp(fmaf(sacc[j][0], 0.125f, pbs[qm0 * 3 + c3])));
            float p1 = tfr(fexp(fmaf(sacc[j][1], 0.125f, pbs[qm0 * 3 + c3b])));
            float p2 = tfr(fexp(fmaf(sacc[j][2], 0.125f, pbs[qm8 * 3 + c3])));
            float p3 = tfr(fexp(fmaf(sacc[j][3], 0.125f, pbs[qm8 * 3 + c3b])));
            lg += p0 + p1; lh += p2 + p3;
            *(float2*)&Pt[qrow * 36 + j * 8 + 2 * tig]       = make_float2(p0, p1);
            *(float2*)&Pt[(qrow + 8) * 36 + j * 8 + 2 * tig] = make_float2(p2, p3);
        }
        __syncwarp();

        // ctx += P V  (tf32 k8; V pre-rounded at source)
#pragma unroll
        for (int kk = 0; kk < 4; kk++) {
            uint32_t a0 = fbits(pbase[kk * 8]);
            uint32_t a1 = fbits(pbase[kk * 8 + 8 * 36]);
            uint32_t a2 = fbits(pbase[kk * 8 + 4]);
            uint32_t a3 = fbits(pbase[kk * 8 + 8 * 36 + 4]);
#pragma unroll
            for (int j = 0; j < 8; j++) {
                const float* vp = &Vsm[buf][(kk * 8 + tig) * 72 + j * 8 + g];
                mma8(cacc[j], a0, a1, a2, a3, fbits(vp[0]), fbits(vp[4 * 72]));
            }
        }
    }

    lg += __shfl_xor_sync(~0u, lg, 1); lg += __shfl_xor_sync(~0u, lg, 2);
    lh += __shfl_xor_sync(~0u, lh, 1); lh += __shfl_xor_sync(~0u, lh, 2);
    float ig = 1.f / lg, ih = 1.f / lh;

    size_t rb = (bT + q0 + qrow) * C_DIM + h * DK;
#pragma unroll
    for (int j = 0; j < 8; j++) {
        int c = j * 8 + 2 * tig;
        *(float2*)&ctx[rb + c] = make_float2(cacc[j][0] * ig, cacc[j][1] * ig);
        *(float2*)&ctx[rb + 8 * C_DIM + c] = make_float2(cacc[j][2] * ih, cacc[j][3] * ih);
    }
}

// ---------------------------------------------------------------------------
// LayerNorm: one block (128 thr) per row of 512.
// ---------------------------------------------------------------------------
__global__ __launch_bounds__(128) void ln_kernel(
    const float* __restrict__ in, const float* __restrict__ g,
    const float* __restrict__ bta, float* __restrict__ out)
{
    __shared__ float r1[4], r2[4];
    const size_t rowb = (size_t)blockIdx.x * C_DIM;
    const int tid = threadIdx.x;

    float4 v = *(const float4*)&in[rowb + (tid << 2)];
    float s = v.x + v.y + v.z + v.w;
#pragma unroll
    for (int off = 16; off; off >>= 1) s += __shfl_xor_sync(~0u, s, off);
    if ((tid & 31) == 0) r1[tid >> 5] = s;
    __syncthreads();
    float mu = (r1[0] + r1[1] + r1[2] + r1[3]) * (1.f / C_DIM);

    float dx = v.x - mu, dy = v.y - mu, dz = v.z - mu, dw = v.w - mu;
    float ss = dx * dx + dy * dy + dz * dz + dw * dw;
#pragma unroll
    for (int off = 16; off; off >>= 1) ss += __shfl_xor_sync(~0u, ss, off);
    if ((tid & 31) == 0) r2[tid >> 5] = ss;
    __syncthreads();
    float inv = rsqrtf((r2[0] + r2[1] + r2[2] + r2[3]) * (1.f / C_DIM) + 1e-5f);

    float4 gg = *(const float4*)&g[tid << 2];
    float4 bb = *(const float4*)&bta[tid << 2];
    float4 o4;
    o4.x = dx * inv * gg.x + bb.x;
    o4.y = dy * inv * gg.y + bb.y;
    o4.z = dz * inv * gg.z + bb.z;
    o4.w = dw * inv * gg.w + bb.w;
    *(float4*)&out[rowb + (tid << 2)] = o4;
}

// ---------------------------------------------------------------------------
extern "C" void kernel_launch(void* const* d_in, const int* in_sizes, int n_in,
                              void* d_out, int out_size)
{
    const float* x  = (const float*)d_in[0];
    const float* Wq = (const float*)d_in[1];
    const float* bq = (const float*)d_in[2];
    const float* Wk = (const float*)d_in[3];
    const float* bk = (const float*)d_in[4];
    const float* Wv = (const float*)d_in[5];
    const float* bv = (const float*)d_in[6];
    const float* Wo = (const float*)d_in[7];
    const float* bo = (const float*)d_in[8];
    const float* pb = (const float*)d_in[9];
    const float* lg = (const float*)d_in[10];
    const float* lb = (const float*)d_in[11];
    float* out = (float*)d_out;

    uint32_t *qb, *kb;
    float *v, *ctx, *y;
    cudaGetSymbolAddress((void**)&qb,  g_Qb);
    cudaGetSymbolAddress((void**)&kb,  g_Kb);
    cudaGetSymbolAddress((void**)&v,   g_V);
    cudaGetSymbolAddress((void**)&ctx, g_CTX);
    cudaGetSymbolAddress((void**)&y,   g_Y);

    qkv_gemm<<<dim3(24, M_ROWS / 128), 256>>>(x, Wq, bq, Wk, bk, Wv, bv,
                                              qb, kb, v);

    attn_mma<<<dim3(T_SEQ / 64, H_NUM, B_SZ), 128>>>(qb, kb, v, pb, ctx);

    wo_gemm<<<dim3(C_DIM / 64, M_ROWS / 128), 256>>>(ctx, Wo, bo, x, y);

    ln_kernel<<<M_ROWS, 128>>>(y, lg, lb, out);
}